// round 17
// baseline (speedup 1.0000x reference)
#include <cuda_runtime.h>
#include <cuda_fp16.h>
#include <cstdint>

// ---------------------------------------------------------------------------
// Scratch (device globals)
// ---------------------------------------------------------------------------
__device__ __half g_q [2u * 2048u * 1024u];
__device__ __half g_k [2u * 2048u * 1024u];
__device__ __half g_v [2u * 2048u * 1024u];
__device__ __half g_yt[2u * 2048u * 1024u];
__device__ __half g_xh   [4096u * 1024u];
__device__ __half g_wqkvh[1024u * 3072u];
__device__ __half g_wprojh[1024u * 1024u];

// ---------------------------------------------------------------------------
// cp.async helpers
// ---------------------------------------------------------------------------
__device__ __forceinline__ uint32_t smem_u32(const void* p) {
    return (uint32_t)__cvta_generic_to_shared(p);
}
__device__ __forceinline__ void cp16(uint32_t dst, const void* src) {
    asm volatile("cp.async.cg.shared.global [%0], [%1], 16;"
                 :: "r"(dst), "l"(src) : "memory");
}
__device__ __forceinline__ void cp_commit() {
    asm volatile("cp.async.commit_group;" ::: "memory");
}
template <int N>
__device__ __forceinline__ void cp_wait() {
    asm volatile("cp.async.wait_group %0;" :: "n"(N) : "memory");
}

// ---------------------------------------------------------------------------
// mma / ldmatrix helpers
// ---------------------------------------------------------------------------
__device__ __forceinline__ void mma16816(float* c, const uint32_t* a,
                                         uint32_t b0, uint32_t b1) {
    asm volatile(
        "mma.sync.aligned.m16n8k16.row.col.f32.f16.f16.f32 "
        "{%0,%1,%2,%3}, {%4,%5,%6,%7}, {%8,%9}, {%0,%1,%2,%3};"
        : "+f"(c[0]), "+f"(c[1]), "+f"(c[2]), "+f"(c[3])
        : "r"(a[0]), "r"(a[1]), "r"(a[2]), "r"(a[3]), "r"(b0), "r"(b1));
}
__device__ __forceinline__ void ldsm4(uint32_t& r0, uint32_t& r1,
                                      uint32_t& r2, uint32_t& r3, uint32_t a) {
    asm volatile("ldmatrix.sync.aligned.m8n8.x4.shared.b16 {%0,%1,%2,%3}, [%4];"
                 : "=r"(r0), "=r"(r1), "=r"(r2), "=r"(r3) : "r"(a));
}
__device__ __forceinline__ void ldsm4t(uint32_t& r0, uint32_t& r1,
                                       uint32_t& r2, uint32_t& r3, uint32_t a) {
    asm volatile("ldmatrix.sync.aligned.m8n8.x4.trans.shared.b16 {%0,%1,%2,%3}, [%4];"
                 : "=r"(r0), "=r"(r1), "=r"(r2), "=r"(r3) : "r"(a));
}

// ---------------------------------------------------------------------------
// Combined fp32 -> fp16 conversion, grid-stride
// ---------------------------------------------------------------------------
#define N8_X  (4096u * 1024u / 8u)
#define N8_WQ (1024u * 3072u / 8u)
#define N8_WP (1024u * 1024u / 8u)
#define N8_TOT (N8_X + N8_WQ + N8_WP)

__global__ void to_half3_kernel(const float* __restrict__ x,
                                const float* __restrict__ wq,
                                const float* __restrict__ wp,
                                __half* __restrict__ xh,
                                __half* __restrict__ wqh,
                                __half* __restrict__ wph)
{
    for (uint32_t i = blockIdx.x * blockDim.x + threadIdx.x; i < N8_TOT;
         i += gridDim.x * blockDim.x) {
        const float* in;
        __half* out;
        uint32_t j;
        if (i < N8_X)              { in = x;  out = xh;  j = i; }
        else if (i < N8_X + N8_WQ) { in = wq; out = wqh; j = i - N8_X; }
        else                       { in = wp; out = wph; j = i - N8_X - N8_WQ; }
        float4 a = ((const float4*)in)[j * 2];
        float4 b = ((const float4*)in)[j * 2 + 1];
        __half h[8];
        h[0] = __float2half_rn(a.x); h[1] = __float2half_rn(a.y);
        h[2] = __float2half_rn(a.z); h[3] = __float2half_rn(a.w);
        h[4] = __float2half_rn(b.x); h[5] = __float2half_rn(b.y);
        h[6] = __float2half_rn(b.z); h[7] = __float2half_rn(b.w);
        ((uint4*)out)[j] = *(uint4*)h;
    }
}

// ---------------------------------------------------------------------------
// FP16 raw-mma GEMM (fp32 accumulate), BK=64, 3-stage cp.async, 2 CTAs/SM.
// Grid-stride TILE loop (wave-quantization fix): grid may be smaller than the
// tile count; CTA bid processes tiles bid, bid+grid, ... (heavy CTAs first).
// Q output scaled by 0.125*log2(e).
// ---------------------------------------------------------------------------
#define G_ALD 72
#define G_BLD 136
#define G_ASZ (128 * G_ALD)
#define G_BSZ (64 * G_BLD)
#define G_STG 3
#define G_SMEM_BYTES (G_STG * (G_ASZ + G_BSZ) * 2)   // 107520

#define Q_SCALE (0.125f * 1.44269504088896340736f)

template <int ROUND_OUT>
__global__ __launch_bounds__(256, 2) void gemm_mma_kernel(
    const __half* __restrict__ A, const __half* __restrict__ B,
    const float* __restrict__ bias,
    void* __restrict__ out0v, void* __restrict__ out1v, void* __restrict__ out2v,
    int M, int N, int K, int n_tiles, int ntx)
{
    extern __shared__ char gsmc[];
    __half* gsm = (__half*)gsmc;
    const uint32_t smb = smem_u32(gsmc);

    const int tid  = threadIdx.x;
    const int wid  = tid >> 5;
    const int lane = tid & 31;
    const int wmi  = wid & 3;
    const int wni  = wid >> 2;

    const int a_row = (lane & 15);
    const int a_col = (lane >> 4) << 3;
    const int b_row = (lane & 7) + (((lane >> 3) & 1) << 3);
    const int b_col = (lane >> 4) << 3;

    const int iters = K >> 6;

    for (int tile = blockIdx.x; tile < n_tiles; tile += gridDim.x) {
        const int m0 = (tile / ntx) * 128;
        const int n0 = (tile % ntx) * 128;

        float cfr[2][8][4];
#pragma unroll
        for (int mi = 0; mi < 2; ++mi)
#pragma unroll
            for (int nt = 0; nt < 8; ++nt)
#pragma unroll
                for (int j = 0; j < 4; ++j) cfr[mi][nt][j] = 0.0f;

        auto issue_stage = [&](int stage) {
            const int s = stage % G_STG;
            const int k0 = stage << 6;
            __half* as = gsm + s * G_ASZ;
            __half* bs = gsm + G_STG * G_ASZ + s * G_BSZ;
#pragma unroll
            for (int t = 0; t < 4; ++t) {
                int f = tid + t * 256;
                int r = f >> 3, c8 = (f & 7) << 3;
                cp16(smem_u32(as + r * G_ALD + c8),
                     A + (size_t)(m0 + r) * K + k0 + c8);
            }
#pragma unroll
            for (int t = 0; t < 4; ++t) {
                int f = tid + t * 256;
                int r = f >> 4, c8 = (f & 15) << 3;
                cp16(smem_u32(bs + r * G_BLD + c8),
                     B + (size_t)(k0 + r) * N + n0 + c8);
            }
            cp_commit();
        };

        issue_stage(0);
        issue_stage(1);
        if (2 < iters) issue_stage(2);
        else           cp_commit();

        for (int it = 0; it < iters; ++it) {
            cp_wait<2>();
            __syncthreads();

            const int s = it % G_STG;
            const uint32_t a_base = smb + (s * G_ASZ
                                  + (wmi * 32 + a_row) * G_ALD + a_col) * 2;
            const uint32_t b_base = smb + (G_STG * G_ASZ + s * G_BSZ
                                  + b_row * G_BLD + wni * 64 + b_col) * 2;

#pragma unroll
            for (int ks = 0; ks < 4; ++ks) {
                uint32_t af[2][4];
#pragma unroll
                for (int mi = 0; mi < 2; ++mi)
                    ldsm4(af[mi][0], af[mi][1], af[mi][2], af[mi][3],
                          a_base + (mi * 16 * G_ALD + ks * 16) * 2);
                uint32_t bf[4][4];
#pragma unroll
                for (int p = 0; p < 4; ++p)
                    ldsm4t(bf[p][0], bf[p][1], bf[p][2], bf[p][3],
                           b_base + (ks * 16 * G_BLD + p * 16) * 2);
#pragma unroll
                for (int mi = 0; mi < 2; ++mi)
#pragma unroll
                    for (int p = 0; p < 4; ++p) {
                        mma16816(cfr[mi][2 * p],     af[mi], bf[p][0], bf[p][1]);
                        mma16816(cfr[mi][2 * p + 1], af[mi], bf[p][2], bf[p][3]);
                    }
            }
            __syncthreads();

            if (it + 3 < iters) issue_stage(it + 3);
            else                cp_commit();
        }

        // ---- Epilogue ----
        const int nc = n0 & 1023;
        const int colw = wni * 64 + 2 * (lane & 3);
        float2 bv[8];
#pragma unroll
        for (int nt = 0; nt < 8; ++nt) {
            bv[nt].x = bias[n0 + colw + nt * 8];
            bv[nt].y = bias[n0 + colw + nt * 8 + 1];
        }
        const int row0 = m0 + wmi * 32 + (lane >> 2);

        if (ROUND_OUT) {
            __half* outp = (n0 < 1024) ? (__half*)out0v
                         : ((n0 < 2048) ? (__half*)out1v : (__half*)out2v);
            const float osc = (n0 < 1024) ? Q_SCALE : 1.0f;
#pragma unroll
            for (int mi = 0; mi < 2; ++mi) {
#pragma unroll
                for (int nt = 0; nt < 8; ++nt) {
                    int col = nc + colw + nt * 8;
                    __half2 v0 = __floats2half2_rn((cfr[mi][nt][0] + bv[nt].x) * osc,
                                                   (cfr[mi][nt][1] + bv[nt].y) * osc);
                    __half2 v1 = __floats2half2_rn((cfr[mi][nt][2] + bv[nt].x) * osc,
                                                   (cfr[mi][nt][3] + bv[nt].y) * osc);
                    *(__half2*)(outp + (size_t)(row0 + mi * 16) * 1024 + col) = v0;
                    *(__half2*)(outp + (size_t)(row0 + mi * 16 + 8) * 1024 + col) = v1;
                }
            }
        } else {
            float* outp = (n0 < 1024) ? (float*)out0v
                        : ((n0 < 2048) ? (float*)out1v : (float*)out2v);
#pragma unroll
            for (int mi = 0; mi < 2; ++mi) {
#pragma unroll
                for (int nt = 0; nt < 8; ++nt) {
                    int col = nc + colw + nt * 8;
                    float2 v0 = { cfr[mi][nt][0] + bv[nt].x, cfr[mi][nt][1] + bv[nt].y };
                    float2 v1 = { cfr[mi][nt][2] + bv[nt].x, cfr[mi][nt][3] + bv[nt].y };
                    *(float2*)(outp + (size_t)(row0 + mi * 16) * 1024 + col) = v0;
                    *(float2*)(outp + (size_t)(row0 + mi * 16 + 8) * 1024 + col) = v1;
                }
            }
        }
        // epilogue touches no smem; next tile's cp.async is safe after the
        // last compute __syncthreads above.
    }
}

// ---------------------------------------------------------------------------
// Flash attention (causal), FA2-style. Br=128, Bc=64, hd=64, 256 thr,
// 2 CTAs/SM, exp2-domain softmax, 3-deep K/V pipeline, global LPT order.
// ---------------------------------------------------------------------------
#define FLD 72
#define FQ_OFF  0
#define FK_OFF  18432
#define FV_OFF  (18432 + 27648)
#define F_SMEM  (18432 + 2 * 27648)  // 73728

__global__ __launch_bounds__(256, 2) void flash_fa2_kernel(
    const __half* __restrict__ Qg, const __half* __restrict__ Kg,
    const __half* __restrict__ Vg, __half* __restrict__ yt)
{
    extern __shared__ char smc[];
    const uint32_t smb = smem_u32(smc);
    const uint32_t kbA[3] = { smb + FK_OFF, smb + FK_OFF + 9216, smb + FK_OFF + 18432 };
    const uint32_t vbA[3] = { smb + FV_OFF, smb + FV_OFF + 9216, smb + FV_OFF + 18432 };

    const int bid  = blockIdx.x;
    const int qt   = 15 - (bid >> 5);
    const int bh   = bid & 31;
    const int tid  = threadIdx.x;
    const int w    = tid >> 5;
    const int lane = tid & 31;

    const int q_row = (lane & 15);
    const int q_col = (lane >> 4) << 3;
    const int k_row = (lane & 7) + ((lane >> 4) << 3);
    const int k_col = ((lane >> 3) & 1) << 3;
    const int v_row = (lane & 7) + (((lane >> 3) & 1) << 3);
    const int v_col = (lane >> 4) << 3;

    const size_t head_off = (size_t)bh * 131072u;
    const __half* qg = Qg + head_off + (size_t)qt * 8192u;
    const __half* kg = Kg + head_off;
    const __half* vg = Vg + head_off;

#pragma unroll
    for (int t = 0; t < 4; ++t) {
        int f = tid + t * 256;
        int rr = f >> 3, c8 = (f & 7) << 3;
        cp16(smb + FQ_OFF + (rr * FLD + c8) * 2, qg + rr * 64 + c8);
    }
    cp_commit();

    auto issue_kv = [&](int kt) {
        const int buf = kt % 3;
        const __half* kp = kg + (size_t)kt * 4096u;
        const __half* vp = vg + (size_t)kt * 4096u;
#pragma unroll
        for (int t = 0; t < 2; ++t) {
            int f = tid + t * 256;
            int rr = f >> 3, c8 = (f & 7) << 3;
            cp16(kbA[buf] + (rr * FLD + c8) * 2, kp + rr * 64 + c8);
            cp16(vbA[buf] + (rr * FLD + c8) * 2, vp + rr * 64 + c8);
        }
        cp_commit();
    };

    const int n_kt = 2 * (qt + 1);
    issue_kv(0);
    issue_kv(1);
    if (2 < n_kt) issue_kv(2);
    else          cp_commit();

    cp_wait<3>();
    __syncthreads();

    uint32_t qf[4][4];
#pragma unroll
    for (int kk = 0; kk < 4; ++kk) {
        uint32_t a = smb + FQ_OFF
                   + ((w * 16 + q_row) * FLD + kk * 16 + q_col) * 2;
        ldsm4(qf[kk][0], qf[kk][1], qf[kk][2], qf[kk][3], a);
    }

    float oacc[8][4];
#pragma unroll
    for (int nt = 0; nt < 8; ++nt)
#pragma unroll
        for (int j = 0; j < 4; ++j) oacc[nt][j] = 0.0f;
    float m_lo = -1e30f, m_hi = -1e30f;
    float l_lo = 0.0f,   l_hi = 0.0f;

    const int row_g_lo = qt * 128 + w * 16 + (lane >> 2);
    const int row_g_hi = row_g_lo + 8;

    for (int kt = 0; kt < n_kt; ++kt) {
        const int buf = kt % 3;
        cp_wait<2>();
        __syncthreads();

        float sacc[8][4];
#pragma unroll
        for (int nt = 0; nt < 8; ++nt)
#pragma unroll
            for (int j = 0; j < 4; ++j) sacc[nt][j] = 0.0f;
#pragma unroll
        for (int p = 0; p < 4; ++p) {
#pragma unroll
            for (int kk = 0; kk < 4; ++kk) {
                uint32_t b0, b1, b2, b3;
                uint32_t a = kbA[buf]
                           + ((p * 16 + k_row) * FLD + kk * 16 + k_col) * 2;
                ldsm4(b0, b1, b2, b3, a);
                mma16816(sacc[2 * p],     qf[kk], b0, b1);
                mma16816(sacc[2 * p + 1], qf[kk], b2, b3);
            }
        }

        if (kt >= 2 * qt) {
            const int cb = kt * 64 + 2 * (lane & 3);
#pragma unroll
            for (int nt = 0; nt < 8; ++nt) {
                int c = cb + nt * 8;
                if (c     > row_g_lo) sacc[nt][0] = -1e30f;
                if (c + 1 > row_g_lo) sacc[nt][1] = -1e30f;
                if (c     > row_g_hi) sacc[nt][2] = -1e30f;
                if (c + 1 > row_g_hi) sacc[nt][3] = -1e30f;
            }
        }

        float mx_lo = -1e30f, mx_hi = -1e30f;
#pragma unroll
        for (int nt = 0; nt < 8; ++nt) {
            mx_lo = fmaxf(mx_lo, fmaxf(sacc[nt][0], sacc[nt][1]));
            mx_hi = fmaxf(mx_hi, fmaxf(sacc[nt][2], sacc[nt][3]));
        }
        mx_lo = fmaxf(mx_lo, __shfl_xor_sync(0xffffffffu, mx_lo, 1));
        mx_lo = fmaxf(mx_lo, __shfl_xor_sync(0xffffffffu, mx_lo, 2));
        mx_hi = fmaxf(mx_hi, __shfl_xor_sync(0xffffffffu, mx_hi, 1));
        mx_hi = fmaxf(mx_hi, __shfl_xor_sync(0xffffffffu, mx_hi, 2));

        const float mn_lo = fmaxf(m_lo, mx_lo);
        const float mn_hi = fmaxf(m_hi, mx_hi);
        const float al_lo = exp2f(m_lo - mn_lo);
        const float al_hi = exp2f(m_hi - mn_hi);
        m_lo = mn_lo; m_hi = mn_hi;

        float sum_lo = 0.0f, sum_hi = 0.0f;
        uint32_t pfr[4][4];
#pragma unroll
        for (int nt = 0; nt < 8; ++nt) {
            float p0 = exp2f(sacc[nt][0] - mn_lo);
            float p1 = exp2f(sacc[nt][1] - mn_lo);
            float p2 = exp2f(sacc[nt][2] - mn_hi);
            float p3 = exp2f(sacc[nt][3] - mn_hi);
            sum_lo += p0 + p1;
            sum_hi += p2 + p3;
            __half2 h01 = __floats2half2_rn(p0, p1);
            __half2 h23 = __floats2half2_rn(p2, p3);
            pfr[nt >> 1][(nt & 1) * 2 + 0] = *(uint32_t*)&h01;
            pfr[nt >> 1][(nt & 1) * 2 + 1] = *(uint32_t*)&h23;
        }
        l_lo = l_lo * al_lo + sum_lo;
        l_hi = l_hi * al_hi + sum_hi;

#pragma unroll
        for (int nt = 0; nt < 8; ++nt) {
            oacc[nt][0] *= al_lo; oacc[nt][1] *= al_lo;
            oacc[nt][2] *= al_hi; oacc[nt][3] *= al_hi;
        }

#pragma unroll
        for (int p = 0; p < 4; ++p) {
#pragma unroll
            for (int t = 0; t < 4; ++t) {
                uint32_t b0, b1, b2, b3;
                uint32_t a = vbA[buf]
                           + ((t * 16 + v_row) * FLD + p * 16 + v_col) * 2;
                ldsm4t(b0, b1, b2, b3, a);
                mma16816(oacc[2 * p],     pfr[t], b0, b1);
                mma16816(oacc[2 * p + 1], pfr[t], b2, b3);
            }
        }

        __syncthreads();
        if (kt + 3 < n_kt) issue_kv(kt + 3);
        else               cp_commit();
    }

    l_lo += __shfl_xor_sync(0xffffffffu, l_lo, 1);
    l_lo += __shfl_xor_sync(0xffffffffu, l_lo, 2);
    l_hi += __shfl_xor_sync(0xffffffffu, l_hi, 1);
    l_hi += __shfl_xor_sync(0xffffffffu, l_hi, 2);
    const float inv_lo = 1.0f / l_lo;
    const float inv_hi = 1.0f / l_hi;

    const int b = bh >> 4;
    const int h = bh & 15;
    const int tq_lo = qt * 128 + w * 16 + (lane >> 2);
    __half* dst_lo = yt + ((size_t)(b * 2048 + tq_lo)) * 1024u + h * 64 + 2 * (lane & 3);
    __half* dst_hi = dst_lo + 8u * 1024u;
#pragma unroll
    for (int nt = 0; nt < 8; ++nt) {
        __half2 vlo = __floats2half2_rn(oacc[nt][0] * inv_lo, oacc[nt][1] * inv_lo);
        __half2 vhi = __floats2half2_rn(oacc[nt][2] * inv_hi, oacc[nt][3] * inv_hi);
        *(__half2*)(dst_lo + nt * 8) = vlo;
        *(__half2*)(dst_hi + nt * 8) = vhi;
    }
}

// ---------------------------------------------------------------------------
// Launch
// ---------------------------------------------------------------------------
extern "C" void kernel_launch(void* const* d_in, const int* in_sizes, int n_in,
                              void* d_out, int out_size)
{
    const float* x     = (const float*)d_in[0];
    const float* Wqkv  = (const float*)d_in[1];
    const float* bqkv  = (const float*)d_in[2];
    const float* Wproj = (const float*)d_in[3];
    const float* bproj = (const float*)d_in[4];
    float* out = (float*)d_out;

    __half *q, *k, *v, *yt, *xh, *wqkvh, *wprojh;
    cudaGetSymbolAddress((void**)&q,  g_q);
    cudaGetSymbolAddress((void**)&k,  g_k);
    cudaGetSymbolAddress((void**)&v,  g_v);
    cudaGetSymbolAddress((void**)&yt, g_yt);
    cudaGetSymbolAddress((void**)&xh, g_xh);
    cudaGetSymbolAddress((void**)&wqkvh, g_wqkvh);
    cudaGetSymbolAddress((void**)&wprojh, g_wprojh);

    const int M = 4096, C = 1024;

    // 0) fp32 -> fp16 conversion
    {
        to_half3_kernel<<<2048, 256>>>(x, Wqkv, Wproj, xh, wqkvh, wprojh);
    }

    cudaFuncSetAttribute(gemm_mma_kernel<1>,
                         cudaFuncAttributeMaxDynamicSharedMemorySize, G_SMEM_BYTES);
    cudaFuncSetAttribute(gemm_mma_kernel<0>,
                         cudaFuncAttributeMaxDynamicSharedMemorySize, G_SMEM_BYTES);

    // 1) QKV projection: 768 tiles on 592 CTAs (2 full waves at 2 CTAs/SM;
    //    CTAs 0..175 take a second tile — heavy-first LPT order)
    {
        gemm_mma_kernel<1><<<592, 256, G_SMEM_BYTES>>>(xh, wqkvh, bqkv,
                                                       q, k, v, M, 3 * C, C,
                                                       768, 24);
    }

    // 2) Flash attention (causal) -> yt (half), LPT-ordered 1-D grid
    {
        cudaFuncSetAttribute(flash_fa2_kernel,
                             cudaFuncAttributeMaxDynamicSharedMemorySize, F_SMEM);
        flash_fa2_kernel<<<512, 256, F_SMEM>>>(q, k, v, yt);
    }

    // 3) Output projection: 256 tiles, single wave — 1 tile per CTA
    {
        gemm_mma_kernel<0><<<256, 256, G_SMEM_BYTES>>>(yt, wprojh, bproj,
                                                       out, out, out, M, C, C,
                                                       256, 8);
    }
}